// round 12
// baseline (speedup 1.0000x reference)
#include <cuda_runtime.h>
#include <cuda_bf16.h>
#include <cstdint>

#define T_ 64
#define B_ 128
#define L_ 64
#define E_ 256
#define H_ 32
#define N_ (T_*B_)

// ---- attn SMEM layout (bytes); 1 n per block, 64 X rows ----
#define XROW 528
#define XH_OFF   0                    // 64 x 528
#define XL_OFF   33792
#define YH_OFF   67584
#define YL_OFF   101376
#define AT_OFF   135168               // 2 bufs x (hi 20480 + lo 20480), row stride 80
#define AT_BUF   40960
#define AT_LO    20480
#define PROB_OFF AT_OFF               // reuse: 64 x 68 f32 = 17408
#define DROPF_OFF 217088              // 64 f32
#define WSUM_OFF  217344              // 64 f32
#define RINV_OFF  217600              // 64 f32
#define ZSH_OFF   217856              // 256 f32
#define ATTN_SMEM 218880

__device__ __nv_bfloat16 g_At_hi[E_*E_];
__device__ __nv_bfloat16 g_At_lo[E_*E_];
__device__ float g_Ccm[E_*E_];
__device__ float g_M[E_*128];               // M[j][g] = sum_f Ccm[j][f]*w_ih[g][f]
__device__ float g_xw[(size_t)N_*128];
__device__ int   g_mask_mode;

// ---------------- helpers ----------------
__device__ __forceinline__ uint32_t smem_u32(const void* p) {
    uint32_t a;
    asm("{ .reg .u64 t; cvta.to.shared.u64 t, %1; cvt.u32.u64 %0, t; }"
        : "=r"(a) : "l"(p));
    return a;
}
__device__ __forceinline__ void sts32(uint32_t a, uint32_t v) {
    asm volatile("st.shared.b32 [%0], %1;" :: "r"(a), "r"(v));
}
__device__ __forceinline__ void sts64(uint32_t a, uint32_t v0, uint32_t v1) {
    asm volatile("st.shared.v2.b32 [%0], {%1, %2};" :: "r"(a), "r"(v0), "r"(v1));
}
__device__ __forceinline__ void ldmx4(uint32_t* r, uint32_t addr) {
    asm volatile("ldmatrix.sync.aligned.m8n8.x4.shared.b16 {%0,%1,%2,%3}, [%4];"
        : "=r"(r[0]), "=r"(r[1]), "=r"(r[2]), "=r"(r[3]) : "r"(addr));
}
#define CP_ASYNC16(dst, src) \
    asm volatile("cp.async.ca.shared.global [%0], [%1], 16;" :: "r"(dst), "l"(src))
#define CP_COMMIT() asm volatile("cp.async.commit_group;" ::: "memory")
#define CP_WAIT0()  asm volatile("cp.async.wait_group 0;" ::: "memory")

// D += A * B^T  (m16n8k16, bf16 in, f32 accum)
__device__ __forceinline__ void mma16816(float* d, const uint32_t* a, const uint32_t* b) {
    asm volatile(
        "mma.sync.aligned.m16n8k16.row.col.f32.bf16.bf16.f32 "
        "{%0,%1,%2,%3}, {%4,%5,%6,%7}, {%8,%9}, {%0,%1,%2,%3};"
        : "+f"(d[0]), "+f"(d[1]), "+f"(d[2]), "+f"(d[3])
        : "r"(a[0]), "r"(a[1]), "r"(a[2]), "r"(a[3]), "r"(b[0]), "r"(b[1]));
}

__device__ __forceinline__ uint32_t pack_hi(float a, float b, float& ra, float& rb) {
    __nv_bfloat162 t = __floats2bfloat162_rn(a, b);
    ra = a - __low2float(t);
    rb = b - __high2float(t);
    return *(uint32_t*)&t;
}
__device__ __forceinline__ uint32_t pack_lo(float a, float b) {
    __nv_bfloat162 t = __floats2bfloat162_rn(a, b);
    return *(uint32_t*)&t;
}

// ---------------------------------------------------------------------------
__global__ void detect_mask_kernel(const void* __restrict__ mask)
{
    const unsigned int* w = (const unsigned int*)mask;
    __shared__ int s_not01, s_notf;
    if (threadIdx.x == 0) { s_not01 = 0; s_notf = 0; }
    __syncthreads();
    int not01 = 0, notf = 0;
    for (int i = threadIdx.x; i < 131072; i += 256) {
        unsigned int v = w[i];
        if (v != 0u && v != 1u) not01 = 1;
        if (v != 0u && v != 0x3F800000u) notf = 1;
    }
    if (not01) atomicOr(&s_not01, 1);
    if (notf)  atomicOr(&s_notf, 1);
    __syncthreads();
    if (threadIdx.x == 0)
        g_mask_mode = (!s_not01) ? 1 : ((!s_notf) ? 2 : 0);
}

// blocks [0,256): At[j][e] -> bf16 hi/lo.  blocks [256,512): Ccm[j][f].
__global__ __launch_bounds__(256) void precompute_kernel(
    const float* __restrict__ in_proj, const float* __restrict__ out_proj)
{
    __shared__ float buf[E_];
    const int b = blockIdx.x, tid = threadIdx.x;
    if (b < E_) {
        const int j = b;
        float acc = 0.f;
        #pragma unroll 4
        for (int f = 0; f < E_; ++f)
            acc = fmaf(in_proj[f*E_ + tid], in_proj[(E_+f)*E_ + j], acc);
        __nv_bfloat16 h = __float2bfloat16_rn(acc);
        g_At_hi[j*E_ + tid] = h;
        g_At_lo[j*E_ + tid] = __float2bfloat16_rn(acc - __bfloat162float(h));
    } else {
        const int f = b - E_;
        buf[tid] = out_proj[f*E_ + tid];
        __syncthreads();
        float acc = 0.f;
        #pragma unroll 4
        for (int e = 0; e < E_; ++e)
            acc = fmaf(buf[e], in_proj[(2*E_+e)*E_ + tid], acc);
        g_Ccm[tid*E_ + f] = acc;
    }
}

// M[j][g] = sum_f Ccm[j][f] * w_ih[g][f]    (grid 256 = j, 128 thr = g)
__global__ __launch_bounds__(128) void precompute2_kernel(const float* __restrict__ w_ih)
{
    __shared__ float cj[E_];
    const int j = blockIdx.x, tid = threadIdx.x;
    cj[tid]       = g_Ccm[j*E_ + tid];
    cj[tid + 128] = g_Ccm[j*E_ + tid + 128];
    __syncthreads();
    float acc = 0.f;
    #pragma unroll 4
    for (int f = 0; f < E_; ++f)
        acc = fmaf(cj[f], w_ih[tid*E_ + f], acc);
    g_M[j*128 + tid] = acc;
}

// ---------------------------------------------------------------------------
// Attention, one row n per block, HMMA bf16-split, ldmatrix fragment loads.
__global__ __launch_bounds__(256, 1) void attn_mma_kernel(
    const float* __restrict__ x, const void* __restrict__ mask)
{
    extern __shared__ char sm[];
    const uint32_t sb = smem_u32(sm);
    const int tid = threadIdx.x;
    const int w = tid >> 5, lane = tid & 31;
    const int qr = lane >> 2, qc = lane & 3;
    const int m0 = (w & 3) * 16;            // m-tile base row
    const int nhalf = (w >> 2) * 128;       // GEMM1 n base
    const int n = blockIdx.x;

    // ldmatrix per-lane address components
    const int lg = lane >> 3, lr = lane & 7;
    const uint32_t a_row = (uint32_t)(m0 + ((lg & 1) << 3) + lr);
    const uint32_t a_byte = (uint32_t)((lg >> 1) << 4);
    const uint32_t b_rloc = (uint32_t)(((lg >> 1) << 3) + lr);
    const uint32_t b_byte = (uint32_t)((lg & 1) << 4);

    float* dropf  = (float*)(sm + DROPF_OFF);
    float* wsm    = (float*)(sm + WSUM_OFF);
    float* rowinv = (float*)(sm + RINV_OFF);
    float* zsh    = (float*)(sm + ZSH_OFF);

    // --- prologue: issue At chunk 0 (K=32 slice) ---
    {
        int j = tid;
        uint32_t d = sb + AT_OFF + j*80;
        const __nv_bfloat16* sh = g_At_hi + j*E_;
        const __nv_bfloat16* sl = g_At_lo + j*E_;
        #pragma unroll
        for (int p = 0; p < 4; ++p) {
            CP_ASYNC16(d + p*16,         sh + p*8);
            CP_ASYNC16(d + AT_LO + p*16, sl + p*8);
        }
    }
    CP_COMMIT();

    // --- mask + wsum init ---
    if (tid < 64) {
        int mode = g_mask_mode;
        size_t idx = (size_t)n * L_ + tid;
        bool obs;
        if (mode == 1)      obs = ((const int*)mask)[idx] != 0;
        else if (mode == 2) obs = ((const float*)mask)[idx] != 0.0f;
        else                obs = ((const unsigned char*)mask)[idx] != 0;
        dropf[tid] = obs ? 0.f : 1.f;
        wsm[tid] = 0.f;
    }

    // --- load X[n] (64x256 f32), split to bf16 hi/lo ---
    {
        const float4* xg = (const float4*)(x + (size_t)n * (L_*E_));
        for (int i = tid; i < 4096; i += 256) {
            float4 v = xg[i];
            int row = i >> 6, c4 = i & 63;
            float la, lb, lc, ld;
            uint32_t h01 = pack_hi(v.x, v.y, la, lb);
            uint32_t h23 = pack_hi(v.z, v.w, lc, ld);
            uint32_t l01 = pack_lo(la, lb);
            uint32_t l23 = pack_lo(lc, ld);
            uint32_t o = row*XROW + c4*8;
            sts64(sb + XH_OFF + o, h01, h23);
            sts64(sb + XL_OFF + o, l01, l23);
        }
    }

    // ===== GEMM1: Y[64,256] = Xsplit @ At^T, K=256 in 8 chunks of 32 =====
    float acc[16][4];
    #pragma unroll
    for (int t = 0; t < 16; ++t)
        #pragma unroll
        for (int r = 0; r < 4; ++r) acc[t][r] = 0.f;

    const uint32_t xh_lm = sb + XH_OFF + a_row*XROW + a_byte;
    const uint32_t xl_lm = xh_lm + (XL_OFF - XH_OFF);

    #pragma unroll 1
    for (int c = 0; c < 8; ++c) {
        CP_WAIT0();
        __syncthreads();
        if (c < 7) {
            int e0 = (c+1)*32;
            uint32_t dst = sb + AT_OFF + ((c+1) & 1)*AT_BUF + tid*80;
            const __nv_bfloat16* sh = g_At_hi + tid*E_ + e0;
            const __nv_bfloat16* sl = g_At_lo + tid*E_ + e0;
            #pragma unroll
            for (int p = 0; p < 4; ++p) {
                CP_ASYNC16(dst + p*16,         sh + p*8);
                CP_ASYNC16(dst + AT_LO + p*16, sl + p*8);
            }
            CP_COMMIT();
        }
        const uint32_t atb = sb + AT_OFF + (c & 1)*AT_BUF;
        #pragma unroll
        for (int sub = 0; sub < 2; ++sub) {
            const uint32_t e_byte = (uint32_t)(c*64 + sub*32);
            uint32_t ah4[4], al4[4];
            ldmx4(ah4, xh_lm + e_byte);
            ldmx4(al4, xl_lm + e_byte);
            #pragma unroll
            for (int pt = 0; pt < 8; ++pt) {
                uint32_t ba = atb + (uint32_t)(nhalf + pt*16 + b_rloc)*80
                            + sub*32 + b_byte;
                uint32_t bh4[4], bl4[4];
                ldmx4(bh4, ba);
                ldmx4(bl4, ba + AT_LO);
                mma16816(acc[2*pt],   ah4, bh4);
                mma16816(acc[2*pt],   ah4, bl4);
                mma16816(acc[2*pt],   al4, bh4);
                mma16816(acc[2*pt+1], ah4, bh4 + 2);
                mma16816(acc[2*pt+1], ah4, bl4 + 2);
                mma16816(acc[2*pt+1], al4, bh4 + 2);
            }
        }
    }

    // --- split Y to bf16 hi/lo in SMEM ---
    #pragma unroll
    for (int nt = 0; nt < 16; ++nt) {
        int col = nhalf + nt*8 + qc*2;
        float r0, r1, r2, r3;
        uint32_t h01 = pack_hi(acc[nt][0], acc[nt][1], r0, r1);
        uint32_t l01 = pack_lo(r0, r1);
        uint32_t h23 = pack_hi(acc[nt][2], acc[nt][3], r2, r3);
        uint32_t l23 = pack_lo(r2, r3);
        uint32_t a0 = sb + YH_OFF + (uint32_t)(m0+qr)*XROW + col*2;
        sts32(a0, h01);
        sts32(a0 + 8*XROW, h23);
        sts32(a0 + (YL_OFF - YH_OFF), l01);
        sts32(a0 + (YL_OFF - YH_OFF) + 8*XROW, l23);
    }
    __syncthreads();

    // ===== GEMM2: S[64,64] = Ysplit @ Xsplit^T, K=256 in 16 chunks =====
    const int nb = (w >> 2) * 32;
    float s2[4][4];
    #pragma unroll
    for (int t = 0; t < 4; ++t)
        #pragma unroll
        for (int r = 0; r < 4; ++r) s2[t][r] = 0.f;

    const uint32_t yh_lm = sb + YH_OFF + a_row*XROW + a_byte;
    const uint32_t yl_lm = yh_lm + (YL_OFF - YH_OFF);

    #pragma unroll 1
    for (int k = 0; k < 16; ++k) {
        const uint32_t j2 = (uint32_t)k * 32;
        uint32_t ah4[4], al4[4];
        ldmx4(ah4, yh_lm + j2);
        ldmx4(al4, yl_lm + j2);
        #pragma unroll
        for (int pt = 0; pt < 2; ++pt) {
            uint32_t ba = sb + XH_OFF + (uint32_t)(nb + pt*16 + b_rloc)*XROW
                        + j2 + b_byte;
            uint32_t bh4[4], bl4[4];
            ldmx4(bh4, ba);
            ldmx4(bl4, ba + (XL_OFF - XH_OFF));
            mma16816(s2[2*pt],   ah4, bh4);
            mma16816(s2[2*pt],   ah4, bl4);
            mma16816(s2[2*pt],   al4, bh4);
            mma16816(s2[2*pt+1], ah4, bh4 + 2);
            mma16816(s2[2*pt+1], ah4, bl4 + 2);
            mma16816(s2[2*pt+1], al4, bh4 + 2);
        }
    }
    __syncthreads();   // all warps done reading X/Y before probs overwrite AT area

    // --- scale + mask, dump S to probs buffer (stride 68 f32) ---
    {
        float* probs = (float*)(sm + PROB_OFF);
        int r0i = m0 + qr, r1i = r0i + 8;
        float dl0 = dropf[r0i], dl1 = dropf[r1i];
        #pragma unroll
        for (int nt = 0; nt < 4; ++nt) {
            int c0 = nb + nt*8 + qc*2;
            float dk0 = dropf[c0], dk1 = dropf[c0+1];
            float v00 = s2[nt][0] * 0.0625f;
            float v01 = s2[nt][1] * 0.0625f;
            float v10 = s2[nt][2] * 0.0625f;
            float v11 = s2[nt][3] * 0.0625f;
            if (dl0 != 0.f && dk0 != 0.f) v00 = -1e9f;
            if (dl0 != 0.f && dk1 != 0.f) v01 = -1e9f;
            if (dl1 != 0.f && dk0 != 0.f) v10 = -1e9f;
            if (dl1 != 0.f && dk1 != 0.f) v11 = -1e9f;
            probs[r0i*68 + c0]     = v00;
            probs[r0i*68 + c0 + 1] = v01;
            probs[r1i*68 + c0]     = v10;
            probs[r1i*68 + c0 + 1] = v11;
        }
    }
    __syncthreads();

    // --- softmax over k (4 lanes per row) ---
    {
        float* probs = (float*)(sm + PROB_OFF);
        int r = tid >> 2, part = tid & 3;
        float* Srow = probs + r*68 + (part << 4);
        float m = -1e30f;
        #pragma unroll
        for (int kk = 0; kk < 16; ++kk) m = fmaxf(m, Srow[kk]);
        m = fmaxf(m, __shfl_xor_sync(0xffffffffu, m, 1));
        m = fmaxf(m, __shfl_xor_sync(0xffffffffu, m, 2));
        float ssum = 0.f;
        #pragma unroll
        for (int kk = 0; kk < 16; ++kk) {
            float p = __expf(Srow[kk] - m);
            Srow[kk] = p; ssum += p;
        }
        ssum += __shfl_xor_sync(0xffffffffu, ssum, 1);
        ssum += __shfl_xor_sync(0xffffffffu, ssum, 2);
        if (part == 0) rowinv[r] = 1.f / ssum;
    }
    __syncthreads();

    // --- column sums of probs ---
    {
        float* probs = (float*)(sm + PROB_OFF);
        int k = tid & 63, seg = tid >> 6;
        float p = 0.f;
        #pragma unroll
        for (int li = 0; li < 16; ++li) {
            int l = (seg << 4) + li;
            p = fmaf(probs[l*68 + k], rowinv[l], p);
        }
        atomicAdd(&wsm[k], p);
    }
    __syncthreads();

    // --- z[e] = sum_k w[k] * x[k][e]  (x = hi + lo) ---
    {
        const __nv_bfloat16* xh = (const __nv_bfloat16*)(sm + XH_OFF);
        const __nv_bfloat16* xl = (const __nv_bfloat16*)(sm + XL_OFF);
        const int e = tid;
        float z = 0.f;
        #pragma unroll 8
        for (int k = 0; k < 64; ++k) {
            float xv = __bfloat162float(xh[k*(XROW/2) + e]) +
                       __bfloat162float(xl[k*(XROW/2) + e]);
            z = fmaf(wsm[k], xv, z);
        }
        zsh[e] = z;
    }
    __syncthreads();

    // --- xw[g] = sum_j z[j] * M[j][g]  -> g_xw ---
    if (tid < 128) {
        const int g = tid;
        float acc2 = 0.f;
        #pragma unroll 4
        for (int j = 0; j < E_; ++j)
            acc2 = fmaf(zsh[j], g_M[j*128 + g], acc2);
        g_xw[(size_t)n*128 + g] = acc2;
    }
}

// ---------------------------------------------------------------------------
// LSTM + critic: one block per env, xw precomputed, only h@w_hh serial.
__global__ __launch_bounds__(128) void lstm_kernel(
    const float* __restrict__ done, const float* __restrict__ h0,
    const float* __restrict__ c0,
    const float* __restrict__ w_hh,
    const float* __restrict__ b_ih, const float* __restrict__ b_hh,
    const float* __restrict__ critic_w, const float* __restrict__ critic_b,
    float* __restrict__ out)
{
    __shared__ float whh[128*36];
    __shared__ float bias[128];
    __shared__ float garr[128];
    __shared__ float hsm[32];
    __shared__ float csm[32];

    const int env = blockIdx.x, tid = threadIdx.x;

    for (int i = tid; i < 128*32; i += 128)
        whh[(i >> 5)*36 + (i & 31)] = w_hh[i];
    bias[tid] = b_ih[tid] + b_hh[tid];
    if (tid < 32) { hsm[tid] = h0[env*H_ + tid]; csm[tid] = c0[env*H_ + tid]; }
    const float cw = (tid < 32) ? critic_w[tid] : 0.f;
    const float cb = critic_b[0];
    __syncthreads();

    const float4* wh = (const float4*)(whh + tid*36);
    float xcur = g_xw[(size_t)env*128 + tid];
    float dcur = done[env];

    for (int t = 0; t < T_; ++t) {
        float xnxt = 0.f, dnxt = 0.f;
        if (t < T_ - 1) {
            int nr = (t+1)*B_ + env;
            xnxt = g_xw[(size_t)nr*128 + tid];
            dnxt = done[nr];
        }
        const float keep = 1.f - dcur;
        if (tid < 32) { hsm[tid] *= keep; csm[tid] *= keep; }
        __syncthreads();

        float acc = bias[tid] + xcur;
        const float4* hv = (const float4*)hsm;
        #pragma unroll
        for (int j4 = 0; j4 < 8; ++j4) {
            float4 a = wh[j4], b = hv[j4];
            acc = fmaf(a.x, b.x, acc); acc = fmaf(a.y, b.y, acc);
            acc = fmaf(a.z, b.z, acc); acc = fmaf(a.w, b.w, acc);
        }
        garr[tid] = (tid >= 64 && tid < 96) ? tanhf(acc)
                                            : (1.f / (1.f + __expf(-acc)));
        __syncthreads();

        if (tid < 32) {
            float c = fmaf(garr[32 + tid], csm[tid], garr[tid] * garr[64 + tid]);
            float h = garr[96 + tid] * tanhf(c);
            csm[tid] = c; hsm[tid] = h;
            float p = h * cw;
            p += __shfl_xor_sync(0xffffffffu, p, 16);
            p += __shfl_xor_sync(0xffffffffu, p, 8);
            p += __shfl_xor_sync(0xffffffffu, p, 4);
            p += __shfl_xor_sync(0xffffffffu, p, 2);
            p += __shfl_xor_sync(0xffffffffu, p, 1);
            if (tid == 0) out[t*B_ + env] = p + cb;
        }
        xcur = xnxt; dcur = dnxt;
    }
}

extern "C" void kernel_launch(void* const* d_in, const int* in_sizes, int n_in,
                              void* d_out, int out_size)
{
    const float* x        = (const float*)d_in[0];
    const float* done     = (const float*)d_in[1];
    const void*  mask     = d_in[2];
    const float* h0       = (const float*)d_in[3];
    const float* c0       = (const float*)d_in[4];
    const float* in_proj  = (const float*)d_in[5];
    const float* out_proj = (const float*)d_in[6];
    const float* w_ih     = (const float*)d_in[7];
    const float* w_hh     = (const float*)d_in[8];
    const float* b_ih     = (const float*)d_in[9];
    const float* b_hh     = (const float*)d_in[10];
    const float* critic_w = (const float*)d_in[11];
    const float* critic_b = (const float*)d_in[12];
    float* out = (float*)d_out;

    cudaFuncSetAttribute(attn_mma_kernel, cudaFuncAttributeMaxDynamicSharedMemorySize, ATTN_SMEM);

    detect_mask_kernel<<<1, 256>>>(mask);
    precompute_kernel<<<2*E_, 256>>>(in_proj, out_proj);
    precompute2_kernel<<<E_, 128>>>(w_ih);
    attn_mma_kernel<<<N_, 256, ATTN_SMEM>>>(x, mask);
    lstm_kernel<<<B_, 128>>>(done, h0, c0, w_hh, b_ih, b_hh,
                             critic_w, critic_b, out);
}

// round 15
// speedup vs baseline: 1.5877x; 1.5877x over previous
#include <cuda_runtime.h>
#include <cuda_bf16.h>
#include <cstdint>

#define T_ 64
#define B_ 128
#define L_ 64
#define E_ 256
#define H_ 32
#define N_ (T_*B_)

// ---- attn SMEM layout (bytes); 1 n per block, 2 blocks/SM ----
#define XROW 528
#define XH_OFF   0                    // 64 x 528
#define XL_OFF   33792
#define XD       (XL_OFF - XH_OFF)
#define AT_OFF   67584                // 2 bufs x (hi 8192 + lo 8192), row stride 32
#define AT_BUF   16384
#define AT_LO    8192
#define PROB_OFF AT_OFF               // overlay: 64 x 68 f32 = 17408 (< 32768)
#define DROPF_OFF 100352              // 64 f32
#define WSUM_OFF  100608              // 64 f32
#define RINV_OFF  100864              // 64 f32
#define ZSH_OFF   101120              // 256 f32
#define ATTN_SMEM 102144

__device__ __nv_bfloat16 g_At_hi[E_*E_];
__device__ __nv_bfloat16 g_At_lo[E_*E_];
__device__ float g_Ccm[E_*E_];
__device__ float g_M[E_*128];               // M[j][g] = sum_f Ccm[j][f]*w_ih[g][f]
__device__ float g_xw[(size_t)N_*128];
__device__ int   g_mask_mode;

// ---------------- helpers ----------------
__device__ __forceinline__ uint32_t smem_u32(const void* p) {
    uint32_t a;
    asm("{ .reg .u64 t; cvta.to.shared.u64 t, %1; cvt.u32.u64 %0, t; }"
        : "=r"(a) : "l"(p));
    return a;
}
__device__ __forceinline__ uint32_t lds32(uint32_t a) {
    uint32_t v;
    asm volatile("ld.shared.b32 %0, [%1];" : "=r"(v) : "r"(a));
    return v;
}
__device__ __forceinline__ void sts64(uint32_t a, uint32_t v0, uint32_t v1) {
    asm volatile("st.shared.v2.b32 [%0], {%1, %2};" :: "r"(a), "r"(v0), "r"(v1));
}
#define CP_ASYNC16(dst, src) \
    asm volatile("cp.async.ca.shared.global [%0], [%1], 16;" :: "r"(dst), "l"(src))
#define CP_COMMIT() asm volatile("cp.async.commit_group;" ::: "memory")
#define CP_WAIT0()  asm volatile("cp.async.wait_group 0;" ::: "memory")

// D += A * B^T  (m16n8k16, bf16 in, f32 accum)
__device__ __forceinline__ void mma16816(float* d, const uint32_t* a, const uint32_t* b) {
    asm volatile(
        "mma.sync.aligned.m16n8k16.row.col.f32.bf16.bf16.f32 "
        "{%0,%1,%2,%3}, {%4,%5,%6,%7}, {%8,%9}, {%0,%1,%2,%3};"
        : "+f"(d[0]), "+f"(d[1]), "+f"(d[2]), "+f"(d[3])
        : "r"(a[0]), "r"(a[1]), "r"(a[2]), "r"(a[3]), "r"(b[0]), "r"(b[1]));
}

__device__ __forceinline__ uint32_t pack_hi(float a, float b, float& ra, float& rb) {
    __nv_bfloat162 t = __floats2bfloat162_rn(a, b);
    ra = a - __low2float(t);
    rb = b - __high2float(t);
    return *(uint32_t*)&t;
}
__device__ __forceinline__ uint32_t pack_lo(float a, float b) {
    __nv_bfloat162 t = __floats2bfloat162_rn(a, b);
    return *(uint32_t*)&t;
}

// ---------------------------------------------------------------------------
__global__ void detect_mask_kernel(const void* __restrict__ mask)
{
    const unsigned int* w = (const unsigned int*)mask;
    __shared__ int s_not01, s_notf;
    if (threadIdx.x == 0) { s_not01 = 0; s_notf = 0; }
    __syncthreads();
    int not01 = 0, notf = 0;
    for (int i = threadIdx.x; i < 131072; i += 256) {
        unsigned int v = w[i];
        if (v != 0u && v != 1u) not01 = 1;
        if (v != 0u && v != 0x3F800000u) notf = 1;
    }
    if (not01) atomicOr(&s_not01, 1);
    if (notf)  atomicOr(&s_notf, 1);
    __syncthreads();
    if (threadIdx.x == 0)
        g_mask_mode = (!s_not01) ? 1 : ((!s_notf) ? 2 : 0);
}

// blocks [0,256): At[j][e] -> bf16 hi/lo.  blocks [256,512): Ccm[j][f].
__global__ __launch_bounds__(256) void precompute_kernel(
    const float* __restrict__ in_proj, const float* __restrict__ out_proj)
{
    __shared__ float buf[E_];
    const int b = blockIdx.x, tid = threadIdx.x;
    if (b < E_) {
        const int j = b;
        float acc = 0.f;
        #pragma unroll 4
        for (int f = 0; f < E_; ++f)
            acc = fmaf(in_proj[f*E_ + tid], in_proj[(E_+f)*E_ + j], acc);
        __nv_bfloat16 h = __float2bfloat16_rn(acc);
        g_At_hi[j*E_ + tid] = h;
        g_At_lo[j*E_ + tid] = __float2bfloat16_rn(acc - __bfloat162float(h));
    } else {
        const int f = b - E_;
        buf[tid] = out_proj[f*E_ + tid];
        __syncthreads();
        float acc = 0.f;
        #pragma unroll 4
        for (int e = 0; e < E_; ++e)
            acc = fmaf(buf[e], in_proj[(2*E_+e)*E_ + tid], acc);
        g_Ccm[tid*E_ + f] = acc;
    }
}

// M[j][g] = sum_f Ccm[j][f] * w_ih[g][f]    (grid 256 = j, 128 thr = g)
__global__ __launch_bounds__(128) void precompute2_kernel(const float* __restrict__ w_ih)
{
    __shared__ float cj[E_];
    const int j = blockIdx.x, tid = threadIdx.x;
    cj[tid]       = g_Ccm[j*E_ + tid];
    cj[tid + 128] = g_Ccm[j*E_ + tid + 128];
    __syncthreads();
    float acc = 0.f;
    #pragma unroll 4
    for (int f = 0; f < E_; ++f)
        acc = fmaf(cj[f], w_ih[tid*E_ + f], acc);
    g_M[j*128 + tid] = acc;
}

// ---------------------------------------------------------------------------
// Attention, one row n per block, HMMA bf16-split, Y kept in registers,
// GEMM2 partial-k with in-place cross-warp-pair reduce. 2 blocks/SM.
// At SMEM rows: stride 32B, the two 16B halves XOR-swapped by (row>>2)&1.
__global__ __launch_bounds__(256, 2) void attn_mma_kernel(
    const float* __restrict__ x, const void* __restrict__ mask)
{
    extern __shared__ char sm[];
    const uint32_t sb = smem_u32(sm);
    const int tid = threadIdx.x;
    const int w = tid >> 5, lane = tid & 31;
    const int qr = lane >> 2, qc = lane & 3;
    const int mt = w & 3, m0 = mt * 16;     // m-tile base row
    const int nh = w >> 2;                  // n/j half (128 each)
    const int nhalf = nh << 7;
    const int n = blockIdx.x;
    const uint32_t s16 = (uint32_t)(((qr >> 2) & 1) << 4);  // reader chunk swizzle

    float* dropf  = (float*)(sm + DROPF_OFF);
    float* wsm    = (float*)(sm + WSUM_OFF);
    float* rowinv = (float*)(sm + RINV_OFF);
    float* zsh    = (float*)(sm + ZSH_OFF);

    // --- prologue: issue At chunk 0 (K=16 slice; 256 j-rows, stride 32B) ---
    {
        uint32_t sw = (uint32_t)(((tid >> 2) & 1) << 4);
        uint32_t d = sb + AT_OFF + tid*32;
        const __nv_bfloat16* sh = g_At_hi + tid*E_;
        const __nv_bfloat16* sl = g_At_lo + tid*E_;
        CP_ASYNC16(d + sw,                sh);
        CP_ASYNC16(d + (16u ^ sw),        sh + 8);
        CP_ASYNC16(d + AT_LO + sw,        sl);
        CP_ASYNC16(d + AT_LO + (16u ^ sw), sl + 8);
    }
    CP_COMMIT();

    // --- mask + wsum init ---
    if (tid < 64) {
        int mode = g_mask_mode;
        size_t idx = (size_t)n * L_ + tid;
        bool obs;
        if (mode == 1)      obs = ((const int*)mask)[idx] != 0;
        else if (mode == 2) obs = ((const float*)mask)[idx] != 0.0f;
        else                obs = ((const unsigned char*)mask)[idx] != 0;
        dropf[tid] = obs ? 0.f : 1.f;
        wsm[tid] = 0.f;
    }

    // --- load X[n] (64x256 f32), split to bf16 hi/lo ---
    {
        const float4* xg = (const float4*)(x + (size_t)n * (L_*E_));
        for (int i = tid; i < 4096; i += 256) {
            float4 v = xg[i];
            int row = i >> 6, c4 = i & 63;
            float la, lb, lc, ld;
            uint32_t h01 = pack_hi(v.x, v.y, la, lb);
            uint32_t h23 = pack_hi(v.z, v.w, lc, ld);
            uint32_t l01 = pack_lo(la, lb);
            uint32_t l23 = pack_lo(lc, ld);
            uint32_t o = row*XROW + c4*8;
            sts64(sb + XH_OFF + o, h01, h23);
            sts64(sb + XL_OFF + o, l01, l23);
        }
    }

    // ===== GEMM1: Y[64,256] = Xsplit @ At^T, K=256 in 16 chunks =====
    float acc[16][4];
    #pragma unroll
    for (int t = 0; t < 16; ++t)
        #pragma unroll
        for (int r = 0; r < 4; ++r) acc[t][r] = 0.f;

    const uint32_t xh_a = sb + XH_OFF + (m0+qr)*XROW + qc*4;
    const uint32_t xl_a = xh_a + XD;

    #pragma unroll 1
    for (int k = 0; k < 16; ++k) {
        CP_WAIT0();
        __syncthreads();
        if (k < 15) {
            int e0 = (k+1)*16;
            uint32_t sw = (uint32_t)(((tid >> 2) & 1) << 4);
            uint32_t dst = sb + AT_OFF + ((k+1) & 1)*AT_BUF + tid*32;
            const __nv_bfloat16* sh = g_At_hi + tid*E_ + e0;
            const __nv_bfloat16* sl = g_At_lo + tid*E_ + e0;
            CP_ASYNC16(dst + sw,                 sh);
            CP_ASYNC16(dst + (16u ^ sw),         sh + 8);
            CP_ASYNC16(dst + AT_LO + sw,         sl);
            CP_ASYNC16(dst + AT_LO + (16u ^ sw), sl + 8);
            CP_COMMIT();
        }
        const uint32_t atb = sb + AT_OFF + (k & 1)*AT_BUF;
        const uint32_t e2 = (uint32_t)k * 32;
        uint32_t a_h[4], a_l[4];
        a_h[0] = lds32(xh_a + e2);
        a_h[1] = lds32(xh_a + e2 + 8*XROW);
        a_h[2] = lds32(xh_a + e2 + 16);
        a_h[3] = lds32(xh_a + e2 + 8*XROW + 16);
        a_l[0] = lds32(xl_a + e2);
        a_l[1] = lds32(xl_a + e2 + 8*XROW);
        a_l[2] = lds32(xl_a + e2 + 16);
        a_l[3] = lds32(xl_a + e2 + 8*XROW + 16);
        #pragma unroll
        for (int nt = 0; nt < 16; ++nt) {
            uint32_t rb = atb + (uint32_t)(nhalf + nt*8 + qr)*32 + qc*4;
            uint32_t bh[2] = { lds32(rb + s16),         lds32(rb + (16u ^ s16)) };
            uint32_t bl[2] = { lds32(rb + AT_LO + s16), lds32(rb + AT_LO + (16u ^ s16)) };
            mma16816(acc[nt], a_h, bh);
            mma16816(acc[nt], a_h, bl);
            mma16816(acc[nt], a_l, bh);
        }
    }

    // ===== GEMM2 (A from registers): partial S over this warp's j-half =====
    float s2[8][4];
    #pragma unroll
    for (int t = 0; t < 8; ++t)
        #pragma unroll
        for (int r = 0; r < 4; ++r) s2[t][r] = 0.f;

    #pragma unroll
    for (int jc = 0; jc < 8; ++jc) {
        float r0, r1;
        uint32_t ah[4], al[4];
        ah[0] = pack_hi(acc[2*jc][0],   acc[2*jc][1],   r0, r1); al[0] = pack_lo(r0, r1);
        ah[1] = pack_hi(acc[2*jc][2],   acc[2*jc][3],   r0, r1); al[1] = pack_lo(r0, r1);
        ah[2] = pack_hi(acc[2*jc+1][0], acc[2*jc+1][1], r0, r1); al[2] = pack_lo(r0, r1);
        ah[3] = pack_hi(acc[2*jc+1][2], acc[2*jc+1][3], r0, r1); al[3] = pack_lo(r0, r1);
        const uint32_t j2 = (uint32_t)(nh*256 + jc*32);
        #pragma unroll
        for (int nt = 0; nt < 8; ++nt) {
            uint32_t ba = sb + XH_OFF + (uint32_t)(nt*8 + qr)*XROW + j2 + qc*4;
            uint32_t bh[2] = { lds32(ba),      lds32(ba + 16) };
            uint32_t bl[2] = { lds32(ba + XD), lds32(ba + XD + 16) };
            mma16816(s2[nt], ah, bh);
            mma16816(s2[nt], ah, bl);
            mma16816(s2[nt], al, bh);
        }
    }
    __syncthreads();   // all GEMM work done; At buffers free for probs overlay

    // --- in-place partial-S combine: nh=1 warps publish raw partials ---
    {
        float* probs = (float*)(sm + PROB_OFF);
        int r0i = m0 + qr, r1i = r0i + 8;
        if (nh == 1) {
            #pragma unroll
            for (int nt = 0; nt < 8; ++nt) {
                int c0 = nt*8 + qc*2;
                probs[r0i*68 + c0]     = s2[nt][0];
                probs[r0i*68 + c0 + 1] = s2[nt][1];
                probs[r1i*68 + c0]     = s2[nt][2];
                probs[r1i*68 + c0 + 1] = s2[nt][3];
            }
        }
        __syncthreads();
        if (nh == 0) {
            float dl0 = dropf[r0i], dl1 = dropf[r1i];
            #pragma unroll
            for (int nt = 0; nt < 8; ++nt) {
                int c0 = nt*8 + qc*2;
                float dk0 = dropf[c0], dk1 = dropf[c0+1];
                float v00 = (s2[nt][0] + probs[r0i*68 + c0])     * 0.0625f;
                float v01 = (s2[nt][1] + probs[r0i*68 + c0 + 1]) * 0.0625f;
                float v10 = (s2[nt][2] + probs[r1i*68 + c0])     * 0.0625f;
                float v11 = (s2[nt][3] + probs[r1i*68 + c0 + 1]) * 0.0625f;
                if (dl0 != 0.f && dk0 != 0.f) v00 = -1e9f;
                if (dl0 != 0.f && dk1 != 0.f) v01 = -1e9f;
                if (dl1 != 0.f && dk0 != 0.f) v10 = -1e9f;
                if (dl1 != 0.f && dk1 != 0.f) v11 = -1e9f;
                probs[r0i*68 + c0]     = v00;
                probs[r0i*68 + c0 + 1] = v01;
                probs[r1i*68 + c0]     = v10;
                probs[r1i*68 + c0 + 1] = v11;
            }
        }
    }
    __syncthreads();

    // --- softmax over k (4 lanes per row) ---
    {
        float* probs = (float*)(sm + PROB_OFF);
        int r = tid >> 2, part = tid & 3;
        float* Srow = probs + r*68 + (part << 4);
        float m = -1e30f;
        #pragma unroll
        for (int kk = 0; kk < 16; ++kk) m = fmaxf(m, Srow[kk]);
        m = fmaxf(m, __shfl_xor_sync(0xffffffffu, m, 1));
        m = fmaxf(m, __shfl_xor_sync(0xffffffffu, m, 2));
        float ssum = 0.f;
        #pragma unroll
        for (int kk = 0; kk < 16; ++kk) {
            float p = __expf(Srow[kk] - m);
            Srow[kk] = p; ssum += p;
        }
        ssum += __shfl_xor_sync(0xffffffffu, ssum, 1);
        ssum += __shfl_xor_sync(0xffffffffu, ssum, 2);
        if (part == 0) rowinv[r] = 1.f / ssum;
    }
    __syncthreads();

    // --- column sums of probs ---
    {
        float* probs = (float*)(sm + PROB_OFF);
        int k = tid & 63, seg = tid >> 6;
        float p = 0.f;
        #pragma unroll
        for (int li = 0; li < 16; ++li) {
            int l = (seg << 4) + li;
            p = fmaf(probs[l*68 + k], rowinv[l], p);
        }
        atomicAdd(&wsm[k], p);
    }
    __syncthreads();

    // --- z[e] = sum_k w[k] * x[k][e]  (x = hi + lo) ---
    {
        const __nv_bfloat16* xh = (const __nv_bfloat16*)(sm + XH_OFF);
        const __nv_bfloat16* xl = (const __nv_bfloat16*)(sm + XL_OFF);
        const int e = tid;
        float z = 0.f;
        #pragma unroll 8
        for (int k = 0; k < 64; ++k) {
            float xv = __bfloat162float(xh[k*(XROW/2) + e]) +
                       __bfloat162float(xl[k*(XROW/2) + e]);
            z = fmaf(wsm[k], xv, z);
        }
        zsh[e] = z;
    }
    __syncthreads();

    // --- xw[g] = sum_j z[j] * M[j][g]  -> g_xw ---
    if (tid < 128) {
        const int g = tid;
        float acc2 = 0.f;
        #pragma unroll 4
        for (int j = 0; j < E_; ++j)
            acc2 = fmaf(zsh[j], g_M[j*128 + g], acc2);
        g_xw[(size_t)n*128 + g] = acc2;
    }
}

// ---------------------------------------------------------------------------
// LSTM + critic: one block per env, xw precomputed, only h@w_hh serial.
__global__ __launch_bounds__(128) void lstm_kernel(
    const float* __restrict__ done, const float* __restrict__ h0,
    const float* __restrict__ c0,
    const float* __restrict__ w_hh,
    const float* __restrict__ b_ih, const float* __restrict__ b_hh,
    const float* __restrict__ critic_w, const float* __restrict__ critic_b,
    float* __restrict__ out)
{
    __shared__ float whh[128*36];
    __shared__ float bias[128];
    __shared__ float garr[128];
    __shared__ float hsm[32];
    __shared__ float csm[32];

    const int env = blockIdx.x, tid = threadIdx.x;

    for (int i = tid; i < 128*32; i += 128)
        whh[(i >> 5)*36 + (i & 31)] = w_hh[i];
    bias[tid] = b_ih[tid] + b_hh[tid];
    if (tid < 32) { hsm[tid] = h0[env*H_ + tid]; csm[tid] = c0[env*H_ + tid]; }
    const float cw = (tid < 32) ? critic_w[tid] : 0.f;
    const float cb = critic_b[0];
    __syncthreads();

    const float4* wh = (const float4*)(whh + tid*36);
    float xcur = g_xw[(size_t)env*128 + tid];
    float dcur = done[env];

    for (int t = 0; t < T_; ++t) {
        float xnxt = 0.f, dnxt = 0.f;
        if (t < T_ - 1) {
            int nr = (t+1)*B_ + env;
            xnxt = g_xw[(size_t)nr*128 + tid];
            dnxt = done[nr];
        }
        const float keep = 1.f - dcur;
        if (tid < 32) { hsm[tid] *= keep; csm[tid] *= keep; }
        __syncthreads();

        float acc = bias[tid] + xcur;
        const float4* hv = (const float4*)hsm;
        #pragma unroll
        for (int j4 = 0; j4 < 8; ++j4) {
            float4 a = wh[j4], b = hv[j4];
            acc = fmaf(a.x, b.x, acc); acc = fmaf(a.y, b.y, acc);
            acc = fmaf(a.z, b.z, acc); acc = fmaf(a.w, b.w, acc);
        }
        garr[tid] = (tid >= 64 && tid < 96) ? tanhf(acc)
                                            : (1.f / (1.f + __expf(-acc)));
        __syncthreads();

        if (tid < 32) {
            float c = fmaf(garr[32 + tid], csm[tid], garr[tid] * garr[64 + tid]);
            float h = garr[96 + tid] * tanhf(c);
            csm[tid] = c; hsm[tid] = h;
            float p = h * cw;
            p += __shfl_xor_sync(0xffffffffu, p, 16);
            p += __shfl_xor_sync(0xffffffffu, p, 8);
            p += __shfl_xor_sync(0xffffffffu, p, 4);
            p += __shfl_xor_sync(0xffffffffu, p, 2);
            p += __shfl_xor_sync(0xffffffffu, p, 1);
            if (tid == 0) out[t*B_ + env] = p + cb;
        }
        xcur = xnxt; dcur = dnxt;
    }
}

extern "C" void kernel_launch(void* const* d_in, const int* in_sizes, int n_in,
                              void* d_out, int out_size)
{
    const float* x        = (const float*)d_in[0];
    const float* done     = (const float*)d_in[1];
    const void*  mask     = d_in[2];
    const float* h0       = (const float*)d_in[3];
    const float* c0       = (const float*)d_in[4];
    const float* in_proj  = (const float*)d_in[5];
    const float* out_proj = (const float*)d_in[6];
    const float* w_ih     = (const float*)d_in[7];
    const float* w_hh     = (const float*)d_in[8];
    const float* b_ih     = (const float*)d_in[9];
    const float* b_hh     = (const float*)d_in[10];
    const float* critic_w = (const float*)d_in[11];
    const float* critic_b = (const float*)d_in[12];
    float* out = (float*)d_out;

    cudaFuncSetAttribute(attn_mma_kernel, cudaFuncAttributeMaxDynamicSharedMemorySize, ATTN_SMEM);

    detect_mask_kernel<<<1, 256>>>(mask);
    precompute_kernel<<<2*E_, 256>>>(in_proj, out_proj);
    precompute2_kernel<<<E_, 128>>>(w_ih);
    attn_mma_kernel<<<N_, 256, ATTN_SMEM>>>(x, mask);
    lstm_kernel<<<B_, 128>>>(done, h0, c0, w_hh, b_ih, b_hh,
                             critic_w, critic_b, out);
}